// round 9
// baseline (speedup 1.0000x reference)
#include <cuda_runtime.h>

// QuantumConvLayer: out[:,2i]   = cos(q[2i]) * cos(pi*x[:,2i])
//                   out[:,2i+1] = out[:,2i]  * cos(q[2i+1] + pi*x[:,2i+1])
// Streaming HBM-bound: 256MB read + 256MB write, zero reuse.
// R9: R8 shape (TPB=512, VPT=4 block-strided coalesced, MLP=4, exact grid,
// one q float4/thread) with ASYMMETRIC cache policy: reads evict-first
// (__ldcs) but stores default write-back, letting the 126MB L2 batch dirty
// writebacks into longer same-direction DRAM bursts (attacks R/W turnaround,
// the suspected cause of the ~6.25 TB/s sustained ceiling).

#ifndef QC_PI
#define QC_PI 3.14159265358979323846f
#endif

#define VPT 4    // float4s per thread
#define TPB 512  // threads per block
#define TILE (TPB * VPT)   // 2048 float4s per block

__global__ void __launch_bounds__(TPB)
qconv_kernel(const float4* __restrict__ x4,
             const float*  __restrict__ q,
             float4* __restrict__ out4)
{
    int base = blockIdx.x * TILE + threadIdx.x;

    // 4 coalesced 128-bit streaming loads, front-batched (MLP=4)
    float4 v0 = __ldcs(x4 + base + 0 * TPB);
    float4 v1 = __ldcs(x4 + base + 1 * TPB);
    float4 v2 = __ldcs(x4 + base + 2 * TPB);
    float4 v3 = __ldcs(x4 + base + 3 * TPB);

    // stride TPB=512 is 0 mod 4 -> all 4 elements share row phase (base & 3)
    const float4* q4 = (const float4*)q;
    float4 qa = __ldg(q4 + (base & 3));   // q[c..c+3], c = 4*(base&3)

    float ce = __cosf(qa.x);   // cos(q[c])
    float cf = __cosf(qa.z);   // cos(q[c+2])

    {
        float a0 = ce * __cosf(QC_PI * v0.x);
        float b0 = a0 * __cosf(fmaf(QC_PI, v0.y, qa.y));
        float a1 = cf * __cosf(QC_PI * v0.z);
        float b1 = a1 * __cosf(fmaf(QC_PI, v0.w, qa.w));
        out4[base + 0 * TPB] = make_float4(a0, b0, a1, b1);   // default .wb store
    }
    {
        float a0 = ce * __cosf(QC_PI * v1.x);
        float b0 = a0 * __cosf(fmaf(QC_PI, v1.y, qa.y));
        float a1 = cf * __cosf(QC_PI * v1.z);
        float b1 = a1 * __cosf(fmaf(QC_PI, v1.w, qa.w));
        out4[base + 1 * TPB] = make_float4(a0, b0, a1, b1);
    }
    {
        float a0 = ce * __cosf(QC_PI * v2.x);
        float b0 = a0 * __cosf(fmaf(QC_PI, v2.y, qa.y));
        float a1 = cf * __cosf(QC_PI * v2.z);
        float b1 = a1 * __cosf(fmaf(QC_PI, v2.w, qa.w));
        out4[base + 2 * TPB] = make_float4(a0, b0, a1, b1);
    }
    {
        float a0 = ce * __cosf(QC_PI * v3.x);
        float b0 = a0 * __cosf(fmaf(QC_PI, v3.y, qa.y));
        float a1 = cf * __cosf(QC_PI * v3.z);
        float b1 = a1 * __cosf(fmaf(QC_PI, v3.w, qa.w));
        out4[base + 3 * TPB] = make_float4(a0, b0, a1, b1);
    }
}

extern "C" void kernel_launch(void* const* d_in, const int* in_sizes, int n_in,
                              void* d_out, int out_size)
{
    const float4* x4 = (const float4*)d_in[0];
    const float*  q  = (const float*)d_in[1];
    float4* out4     = (float4*)d_out;

    int n_elems = in_sizes[0];   // B * 16 = 67108864
    int n4 = n_elems >> 2;       // 16777216 float4s; divisible by TILE=2048

    int blocks = n4 / TILE;      // 8192, exact
    qconv_kernel<<<blocks, TPB>>>(x4, q, out4);
}

// round 10
// speedup vs baseline: 1.0008x; 1.0008x over previous
#include <cuda_runtime.h>

// QuantumConvLayer: out[:,2i]   = cos(q[2i]) * cos(pi*x[:,2i])
//                   out[:,2i+1] = out[:,2i]  * cos(q[2i+1] + pi*x[:,2i+1])
// Streaming HBM-bound: 256MB read + 256MB write, zero reuse.
// R10: 256-bit global accesses (sm_103a LDG.E.256 / STG.256 via v8.f32 PTX).
// Each thread: two 32B chunks (64B in flight, front-batched), block-strided
// so each warp-instruction covers 1024 contiguous bytes. Halves LSU issues
// and L1tex wavefronts per byte vs LDG.128. Exact grid, zero predicates,
// row phase shared across both chunks -> one q float4 pair per thread.

#ifndef QC_PI
#define QC_PI 3.14159265358979323846f
#endif

#define TPB 256   // threads per block
#define CPT 2     // 8-float chunks per thread
#define TILE_CH (TPB * CPT)   // 512 chunks (4096 floats) per block

__device__ __forceinline__ void ldg256(const float* p, float r[8])
{
    asm volatile("ld.global.nc.v8.f32 {%0,%1,%2,%3,%4,%5,%6,%7}, [%8];"
                 : "=f"(r[0]), "=f"(r[1]), "=f"(r[2]), "=f"(r[3]),
                   "=f"(r[4]), "=f"(r[5]), "=f"(r[6]), "=f"(r[7])
                 : "l"(p));
}

__device__ __forceinline__ void stg256(float* p, const float r[8])
{
    asm volatile("st.global.v8.f32 [%0], {%1,%2,%3,%4,%5,%6,%7,%8};"
                 :: "l"(p),
                    "f"(r[0]), "f"(r[1]), "f"(r[2]), "f"(r[3]),
                    "f"(r[4]), "f"(r[5]), "f"(r[6]), "f"(r[7])
                 : "memory");
}

__global__ void __launch_bounds__(TPB)
qconv_kernel(const float* __restrict__ x,
             const float* __restrict__ q,
             float* __restrict__ out)
{
    // chunk index: 8 floats per chunk, warp-contiguous (lane i -> 32B apart)
    int c0 = blockIdx.x * TILE_CH + threadIdx.x;
    int c1 = c0 + TPB;

    // two 256-bit loads front-batched (64B in flight per thread)
    float v0[8], v1[8];
    ldg256(x + (size_t)c0 * 8, v0);
    ldg256(x + (size_t)c1 * 8, v1);

    // chunk c covers columns (8c .. 8c+7) mod 16 -> phase = (c & 1) * 8.
    // TPB=256 even -> c0, c1 share phase. One pair of q float4 loads.
    const float4* q4 = (const float4*)q;
    int ph = (c0 & 1) << 1;            // 0 or 2 (float4 index)
    float4 qa = __ldg(q4 + ph);        // q[8p .. 8p+3]
    float4 qb = __ldg(q4 + ph + 1);    // q[8p+4 .. 8p+7]

    float ca = __cosf(qa.x);   // cos(q[c+0])
    float cb = __cosf(qa.z);   // cos(q[c+2])
    float cc = __cosf(qb.x);   // cos(q[c+4])
    float cd = __cosf(qb.z);   // cos(q[c+6])

    float r0[8], r1[8];

    // chunk 0: pairs (0,1)(2,3)(4,5)(6,7) with q pairs qa.xy qa.zw qb.xy qb.zw
    r0[0] = ca * __cosf(QC_PI * v0[0]);
    r0[1] = r0[0] * __cosf(fmaf(QC_PI, v0[1], qa.y));
    r0[2] = cb * __cosf(QC_PI * v0[2]);
    r0[3] = r0[2] * __cosf(fmaf(QC_PI, v0[3], qa.w));
    r0[4] = cc * __cosf(QC_PI * v0[4]);
    r0[5] = r0[4] * __cosf(fmaf(QC_PI, v0[5], qb.y));
    r0[6] = cd * __cosf(QC_PI * v0[6]);
    r0[7] = r0[6] * __cosf(fmaf(QC_PI, v0[7], qb.w));

    r1[0] = ca * __cosf(QC_PI * v1[0]);
    r1[1] = r1[0] * __cosf(fmaf(QC_PI, v1[1], qa.y));
    r1[2] = cb * __cosf(QC_PI * v1[2]);
    r1[3] = r1[2] * __cosf(fmaf(QC_PI, v1[3], qa.w));
    r1[4] = cc * __cosf(QC_PI * v1[4]);
    r1[5] = r1[4] * __cosf(fmaf(QC_PI, v1[5], qb.y));
    r1[6] = cd * __cosf(QC_PI * v1[6]);
    r1[7] = r1[6] * __cosf(fmaf(QC_PI, v1[7], qb.w));

    stg256(out + (size_t)c0 * 8, r0);
    stg256(out + (size_t)c1 * 8, r1);
}

extern "C" void kernel_launch(void* const* d_in, const int* in_sizes, int n_in,
                              void* d_out, int out_size)
{
    const float* x   = (const float*)d_in[0];
    const float* q   = (const float*)d_in[1];
    float* out       = (float*)d_out;

    int n_elems = in_sizes[0];      // B * 16 = 67108864
    int n_chunks = n_elems >> 3;    // 8388608 chunks; divisible by TILE_CH=512

    int blocks = n_chunks / TILE_CH;   // 16384, exact
    qconv_kernel<<<blocks, TPB>>>(x, q, out);
}

// round 11
// speedup vs baseline: 1.0019x; 1.0012x over previous
#include <cuda_runtime.h>

// QuantumConvLayer: out[:,2i]   = cos(q[2i]) * cos(pi*x[:,2i])
//                   out[:,2i+1] = out[:,2i]  * cos(q[2i+1] + pi*x[:,2i+1])
// Streaming HBM-bound: 256MB read + 256MB write, zero reuse.
//
// R11 (final): 256-bit global accesses (sm_103a LDG.E.256/STG.256) WITH
// L2::evict_first policy both directions — minimal instructions/byte, no L2
// pollution across graph replays. Two 32B chunks per thread, front-batched
// (64B in flight), warp-instruction covers 1024 contiguous bytes. Exact
// grid, zero predicates, row phase shared -> one q float4 pair per thread.
//
// Measured across R1-R10: every well-formed variant benches 81.95-82.43us
// = 512MB / ~6.25TB/s sustained HBM; single-shot (ncu) 73.5-74.8us at
// 80.5-82.5% DRAM. This kernel is the best-instruction-economy member of
// that floor-limited family.

#ifndef QC_PI
#define QC_PI 3.14159265358979323846f
#endif

#define TPB 256   // threads per block
#define CPT 2     // 8-float chunks per thread
#define TILE_CH (TPB * CPT)   // 512 chunks (4096 floats) per block

__device__ __forceinline__ void ldg256_ef(const float* p, float r[8])
{
    asm volatile("ld.global.nc.L2::evict_first.v8.f32 "
                 "{%0,%1,%2,%3,%4,%5,%6,%7}, [%8];"
                 : "=f"(r[0]), "=f"(r[1]), "=f"(r[2]), "=f"(r[3]),
                   "=f"(r[4]), "=f"(r[5]), "=f"(r[6]), "=f"(r[7])
                 : "l"(p));
}

__device__ __forceinline__ void stg256_ef(float* p, const float r[8])
{
    asm volatile("st.global.L2::evict_first.v8.f32 "
                 "[%0], {%1,%2,%3,%4,%5,%6,%7,%8};"
                 :: "l"(p),
                    "f"(r[0]), "f"(r[1]), "f"(r[2]), "f"(r[3]),
                    "f"(r[4]), "f"(r[5]), "f"(r[6]), "f"(r[7])
                 : "memory");
}

__global__ void __launch_bounds__(TPB)
qconv_kernel(const float* __restrict__ x,
             const float* __restrict__ q,
             float* __restrict__ out)
{
    // chunk index: 8 floats per chunk, warp-contiguous (lane i -> 32B apart)
    int c0 = blockIdx.x * TILE_CH + threadIdx.x;
    int c1 = c0 + TPB;

    // two 256-bit loads front-batched (64B in flight per thread)
    float v0[8], v1[8];
    ldg256_ef(x + (size_t)c0 * 8, v0);
    ldg256_ef(x + (size_t)c1 * 8, v1);

    // chunk c covers columns (8c .. 8c+7) mod 16 -> phase = (c & 1).
    // TPB=256 even -> c0, c1 share phase. One pair of q float4 loads.
    const float4* q4 = (const float4*)q;
    int ph = (c0 & 1) << 1;            // 0 or 2 (float4 index)
    float4 qa = __ldg(q4 + ph);        // q[8p .. 8p+3]
    float4 qb = __ldg(q4 + ph + 1);    // q[8p+4 .. 8p+7]

    float ca = __cosf(qa.x);   // cos(q[c+0])
    float cb = __cosf(qa.z);   // cos(q[c+2])
    float cc = __cosf(qb.x);   // cos(q[c+4])
    float cd = __cosf(qb.z);   // cos(q[c+6])

    float r0[8], r1[8];

    r0[0] = ca * __cosf(QC_PI * v0[0]);
    r0[1] = r0[0] * __cosf(fmaf(QC_PI, v0[1], qa.y));
    r0[2] = cb * __cosf(QC_PI * v0[2]);
    r0[3] = r0[2] * __cosf(fmaf(QC_PI, v0[3], qa.w));
    r0[4] = cc * __cosf(QC_PI * v0[4]);
    r0[5] = r0[4] * __cosf(fmaf(QC_PI, v0[5], qb.y));
    r0[6] = cd * __cosf(QC_PI * v0[6]);
    r0[7] = r0[6] * __cosf(fmaf(QC_PI, v0[7], qb.w));

    r1[0] = ca * __cosf(QC_PI * v1[0]);
    r1[1] = r1[0] * __cosf(fmaf(QC_PI, v1[1], qa.y));
    r1[2] = cb * __cosf(QC_PI * v1[2]);
    r1[3] = r1[2] * __cosf(fmaf(QC_PI, v1[3], qa.w));
    r1[4] = cc * __cosf(QC_PI * v1[4]);
    r1[5] = r1[4] * __cosf(fmaf(QC_PI, v1[5], qb.y));
    r1[6] = cd * __cosf(QC_PI * v1[6]);
    r1[7] = r1[6] * __cosf(fmaf(QC_PI, v1[7], qb.w));

    stg256_ef(out + (size_t)c0 * 8, r0);
    stg256_ef(out + (size_t)c1 * 8, r1);
}

extern "C" void kernel_launch(void* const* d_in, const int* in_sizes, int n_in,
                              void* d_out, int out_size)
{
    const float* x = (const float*)d_in[0];
    const float* q = (const float*)d_in[1];
    float* out     = (float*)d_out;

    int n_elems  = in_sizes[0];     // B * 16 = 67108864
    int n_chunks = n_elems >> 3;    // 8388608 chunks; divisible by TILE_CH=512

    int blocks = n_chunks / TILE_CH;   // 16384, exact
    qconv_kernel<<<blocks, TPB>>>(x, q, out);
}

// round 12
// speedup vs baseline: 1.0094x; 1.0074x over previous
#include <cuda_runtime.h>

// QuantumConvLayer: out[:,2i]   = cos(q[2i]) * cos(pi*x[:,2i])
//                   out[:,2i+1] = out[:,2i]  * cos(q[2i+1] + pi*x[:,2i+1])
// Streaming HBM-bound: 256MB read + 256MB write, zero reuse.
//
// R12: TPB=512 (the shape of both bottom-of-band bench results, R4/R8)
// combined with 256-bit global accesses (best instruction economy, R10/R11).
// Two 32B chunks per thread, front-batched (64B in flight), each warp
// instruction covers 1024 contiguous bytes; 4096-float contiguous tile per
// block. Exact grid (8192 blocks), zero predicates, shared row phase ->
// one q float4 pair per thread.
//
// Context: R1-R11 establish a sustained-HBM bench floor of ~82.0-82.4us
// (512MB / ~6.24TB/s); single-shot ncu 73.5-75.4us at 80.5-82.5% DRAM.

#ifndef QC_PI
#define QC_PI 3.14159265358979323846f
#endif

#define TPB 512   // threads per block
#define CPT 2     // 8-float chunks per thread
#define TILE_CH (TPB * CPT)   // 1024 chunks (8192 floats) per block

__device__ __forceinline__ void ldg256_ef(const float* p, float r[8])
{
    asm volatile("ld.global.nc.L2::evict_first.v8.f32 "
                 "{%0,%1,%2,%3,%4,%5,%6,%7}, [%8];"
                 : "=f"(r[0]), "=f"(r[1]), "=f"(r[2]), "=f"(r[3]),
                   "=f"(r[4]), "=f"(r[5]), "=f"(r[6]), "=f"(r[7])
                 : "l"(p));
}

__device__ __forceinline__ void stg256_ef(float* p, const float r[8])
{
    asm volatile("st.global.L2::evict_first.v8.f32 "
                 "[%0], {%1,%2,%3,%4,%5,%6,%7,%8};"
                 :: "l"(p),
                    "f"(r[0]), "f"(r[1]), "f"(r[2]), "f"(r[3]),
                    "f"(r[4]), "f"(r[5]), "f"(r[6]), "f"(r[7])
                 : "memory");
}

__global__ void __launch_bounds__(TPB)
qconv_kernel(const float* __restrict__ x,
             const float* __restrict__ q,
             float* __restrict__ out)
{
    // chunk index: 8 floats per chunk, warp-contiguous (lane i -> 32B apart)
    int c0 = blockIdx.x * TILE_CH + threadIdx.x;
    int c1 = c0 + TPB;

    // two 256-bit loads front-batched (64B in flight per thread)
    float v0[8], v1[8];
    ldg256_ef(x + (size_t)c0 * 8, v0);
    ldg256_ef(x + (size_t)c1 * 8, v1);

    // chunk c covers columns (8c .. 8c+7) mod 16 -> phase = c & 1.
    // TPB=512 even -> c0, c1 share phase. One pair of q float4 loads.
    const float4* q4 = (const float4*)q;
    int ph = (c0 & 1) << 1;            // 0 or 2 (float4 index)
    float4 qa = __ldg(q4 + ph);        // q[8p .. 8p+3]
    float4 qb = __ldg(q4 + ph + 1);    // q[8p+4 .. 8p+7]

    float ca = __cosf(qa.x);   // cos(q[c+0])
    float cb = __cosf(qa.z);   // cos(q[c+2])
    float cc = __cosf(qb.x);   // cos(q[c+4])
    float cd = __cosf(qb.z);   // cos(q[c+6])

    float r0[8], r1[8];

    r0[0] = ca * __cosf(QC_PI * v0[0]);
    r0[1] = r0[0] * __cosf(fmaf(QC_PI, v0[1], qa.y));
    r0[2] = cb * __cosf(QC_PI * v0[2]);
    r0[3] = r0[2] * __cosf(fmaf(QC_PI, v0[3], qa.w));
    r0[4] = cc * __cosf(QC_PI * v0[4]);
    r0[5] = r0[4] * __cosf(fmaf(QC_PI, v0[5], qb.y));
    r0[6] = cd * __cosf(QC_PI * v0[6]);
    r0[7] = r0[6] * __cosf(fmaf(QC_PI, v0[7], qb.w));

    r1[0] = ca * __cosf(QC_PI * v1[0]);
    r1[1] = r1[0] * __cosf(fmaf(QC_PI, v1[1], qa.y));
    r1[2] = cb * __cosf(QC_PI * v1[2]);
    r1[3] = r1[2] * __cosf(fmaf(QC_PI, v1[3], qa.w));
    r1[4] = cc * __cosf(QC_PI * v1[4]);
    r1[5] = r1[4] * __cosf(fmaf(QC_PI, v1[5], qb.y));
    r1[6] = cd * __cosf(QC_PI * v1[6]);
    r1[7] = r1[6] * __cosf(fmaf(QC_PI, v1[7], qb.w));

    stg256_ef(out + (size_t)c0 * 8, r0);
    stg256_ef(out + (size_t)c1 * 8, r1);
}

extern "C" void kernel_launch(void* const* d_in, const int* in_sizes, int n_in,
                              void* d_out, int out_size)
{
    const float* x = (const float*)d_in[0];
    const float* q = (const float*)d_in[1];
    float* out     = (float*)d_out;

    int n_elems  = in_sizes[0];     // B * 16 = 67108864
    int n_chunks = n_elems >> 3;    // 8388608 chunks; divisible by TILE_CH=1024

    int blocks = n_chunks / TILE_CH;   // 8192, exact
    qconv_kernel<<<blocks, TPB>>>(x, q, out);
}

// round 13
// speedup vs baseline: 1.0284x; 1.0188x over previous
#include <cuda_runtime.h>

// QuantumConvLayer: out[:,2i]   = cos(q[2i]) * cos(pi*x[:,2i])
//                   out[:,2i+1] = out[:,2i]  * cos(q[2i+1] + pi*x[:,2i+1])
// Streaming HBM-bound: 256MB read + 256MB write, zero reuse.
//
// R13: continue the measured bench gradient (bigger blocks x wider access):
//   TPB256/128b ~82.3 -> TPB512/128b ~81.95 -> TPB512/256b 81.63 (R12 best)
// Now TPB=1024 + 256-bit, CPT=2: 8192-float contiguous tile per block,
// grid 4096, 32KB per-CTA footprint per direction (max DRAM-scheduler
// contiguity). Same in-flight/thread (64B) and occupancy (~50%) as R12.
// Exact grid, zero predicates, shared row phase -> one q pair per thread.

#ifndef QC_PI
#define QC_PI 3.14159265358979323846f
#endif

#define TPB 1024  // threads per block
#define CPT 2     // 8-float chunks per thread
#define TILE_CH (TPB * CPT)   // 2048 chunks (16384 floats) per block

__device__ __forceinline__ void ldg256_ef(const float* p, float r[8])
{
    asm volatile("ld.global.nc.L2::evict_first.v8.f32 "
                 "{%0,%1,%2,%3,%4,%5,%6,%7}, [%8];"
                 : "=f"(r[0]), "=f"(r[1]), "=f"(r[2]), "=f"(r[3]),
                   "=f"(r[4]), "=f"(r[5]), "=f"(r[6]), "=f"(r[7])
                 : "l"(p));
}

__device__ __forceinline__ void stg256_ef(float* p, const float r[8])
{
    asm volatile("st.global.L2::evict_first.v8.f32 "
                 "[%0], {%1,%2,%3,%4,%5,%6,%7,%8};"
                 :: "l"(p),
                    "f"(r[0]), "f"(r[1]), "f"(r[2]), "f"(r[3]),
                    "f"(r[4]), "f"(r[5]), "f"(r[6]), "f"(r[7])
                 : "memory");
}

__global__ void __launch_bounds__(TPB)
qconv_kernel(const float* __restrict__ x,
             const float* __restrict__ q,
             float* __restrict__ out)
{
    // chunk index: 8 floats per chunk, warp-contiguous (lane i -> 32B apart)
    int c0 = blockIdx.x * TILE_CH + threadIdx.x;
    int c1 = c0 + TPB;

    // two 256-bit loads front-batched (64B in flight per thread)
    float v0[8], v1[8];
    ldg256_ef(x + (size_t)c0 * 8, v0);
    ldg256_ef(x + (size_t)c1 * 8, v1);

    // chunk c covers columns (8c .. 8c+7) mod 16 -> phase = c & 1.
    // TPB=1024 even -> c0, c1 share phase. One pair of q float4 loads.
    const float4* q4 = (const float4*)q;
    int ph = (c0 & 1) << 1;            // 0 or 2 (float4 index)
    float4 qa = __ldg(q4 + ph);        // q[8p .. 8p+3]
    float4 qb = __ldg(q4 + ph + 1);    // q[8p+4 .. 8p+7]

    float ca = __cosf(qa.x);   // cos(q[c+0])
    float cb = __cosf(qa.z);   // cos(q[c+2])
    float cc = __cosf(qb.x);   // cos(q[c+4])
    float cd = __cosf(qb.z);   // cos(q[c+6])

    float r0[8], r1[8];

    r0[0] = ca * __cosf(QC_PI * v0[0]);
    r0[1] = r0[0] * __cosf(fmaf(QC_PI, v0[1], qa.y));
    r0[2] = cb * __cosf(QC_PI * v0[2]);
    r0[3] = r0[2] * __cosf(fmaf(QC_PI, v0[3], qa.w));
    r0[4] = cc * __cosf(QC_PI * v0[4]);
    r0[5] = r0[4] * __cosf(fmaf(QC_PI, v0[5], qb.y));
    r0[6] = cd * __cosf(QC_PI * v0[6]);
    r0[7] = r0[6] * __cosf(fmaf(QC_PI, v0[7], qb.w));

    r1[0] = ca * __cosf(QC_PI * v1[0]);
    r1[1] = r1[0] * __cosf(fmaf(QC_PI, v1[1], qa.y));
    r1[2] = cb * __cosf(QC_PI * v1[2]);
    r1[3] = r1[2] * __cosf(fmaf(QC_PI, v1[3], qa.w));
    r1[4] = cc * __cosf(QC_PI * v1[4]);
    r1[5] = r1[4] * __cosf(fmaf(QC_PI, v1[5], qb.y));
    r1[6] = cd * __cosf(QC_PI * v1[6]);
    r1[7] = r1[6] * __cosf(fmaf(QC_PI, v1[7], qb.w));

    stg256_ef(out + (size_t)c0 * 8, r0);
    stg256_ef(out + (size_t)c1 * 8, r1);
}

extern "C" void kernel_launch(void* const* d_in, const int* in_sizes, int n_in,
                              void* d_out, int out_size)
{
    const float* x = (const float*)d_in[0];
    const float* q = (const float*)d_in[1];
    float* out     = (float*)d_out;

    int n_elems  = in_sizes[0];     // B * 16 = 67108864
    int n_chunks = n_elems >> 3;    // 8388608 chunks; divisible by TILE_CH=2048

    int blocks = n_chunks / TILE_CH;   // 4096, exact
    qconv_kernel<<<blocks, TPB>>>(x, q, out);
}